// round 1
// baseline (speedup 1.0000x reference)
#include <cuda_runtime.h>

// Problem constants
#define B       8
#define C       64
#define H       256
#define Wd      256
#define G       8
#define FPG     8
#define OCPG    8
#define KS      3
#define REPD    32
#define NK      (C * KS * KS)        // 576 per batch
#define PLANE   (H * Wd)             // 65536

// Tile config
#define TX      64
#define TY      32
#define NTHR    256
#define HALO_W  (TX + 2)             // 66
#define HALO_H  (TY + 2)             // 34

// Scratch for per-sample dynamic kernels: [B, OUT_CH, 3, 3] = 8*576 floats
__device__ float g_kw[B * NK];

// ---------------------------------------------------------------------------
// Kernel 1: kw[b,i] = leaky_relu( rep[b,:] . W[i,:], 0.1 )
// ---------------------------------------------------------------------------
__global__ void gen_kernels(const float* __restrict__ rep,
                            const float* __restrict__ W) {
    const int b = blockIdx.x;
    __shared__ float r[REPD];
    if (threadIdx.x < REPD) r[threadIdx.x] = rep[b * REPD + threadIdx.x];
    __syncthreads();
    const int i = threadIdx.x;
    if (i < NK) {
        const float* wrow = W + (size_t)i * REPD;
        float acc = 0.f;
#pragma unroll
        for (int j = 0; j < REPD; ++j) acc = fmaf(r[j], wrow[j], acc);
        g_kw[b * NK + i] = acc > 0.f ? acc : 0.1f * acc;
    }
}

// ---------------------------------------------------------------------------
// Kernel 2: fused channel-sum + 3x3 dynamic conv (reflect pad)
// grid: (W/TX, H/TY, B*G), block: 256 threads
// ---------------------------------------------------------------------------
__global__ __launch_bounds__(NTHR, 2)
void dyn_conv(const float* __restrict__ x, float* __restrict__ out) {
    const int bg = blockIdx.z;
    const int b  = bg >> 3;
    const int g  = bg & 7;
    const int x0 = blockIdx.x * TX;
    const int y0 = blockIdx.y * TY;
    const int t  = threadIdx.x;

    __shared__ float S[HALO_H * HALO_W];   // channel-summed halo tile
    __shared__ float wsh[OCPG * KS * KS];  // 72 weights for this (b,g)

    if (t < OCPG * KS * KS)
        wsh[t] = g_kw[b * NK + g * (OCPG * KS * KS) + t];

    // ---- Phase 1: sum 8 group channels into smem halo tile ----
    const float* xbase = x + ((size_t)(b * C + g * FPG)) * PLANE;
    const int total = HALO_H * HALO_W;     // 2244
    for (int idx = t; idx < total; idx += NTHR) {
        const int r = idx / HALO_W;
        const int c = idx - r * HALO_W;
        int yy = y0 - 1 + r;
        yy = (yy < 0) ? -yy : yy;
        yy = (yy >= H) ? (2 * H - 2 - yy) : yy;
        int xx = x0 - 1 + c;
        xx = (xx < 0) ? -xx : xx;
        xx = (xx >= Wd) ? (2 * Wd - 2 - xx) : xx;
        const size_t off = (size_t)yy * Wd + xx;
        float s = 0.f;
#pragma unroll
        for (int ch = 0; ch < FPG; ++ch)
            s += xbase[(size_t)ch * PLANE + off];
        S[idx] = s;
    }
    __syncthreads();

    // ---- Phase 2: 3x3 conv, 8 output channels, 8 rows per thread ----
    float wr[OCPG * KS * KS];
#pragma unroll
    for (int i = 0; i < OCPG * KS * KS; ++i) wr[i] = wsh[i];

    const int tx  = t & (TX - 1);
    const int ty0 = t >> 6;                // 0..3

    float* obase = out + ((size_t)(b * C + g * OCPG)) * PLANE
                       + (size_t)y0 * Wd + x0 + tx;

#pragma unroll
    for (int j = 0; j < 8; ++j) {
        const int ty = ty0 + j * 4;        // 0..31
        float acc[OCPG];
#pragma unroll
        for (int oo = 0; oo < OCPG; ++oo) acc[oo] = 0.f;

#pragma unroll
        for (int dy = 0; dy < KS; ++dy) {
            const float* srow = &S[(ty + dy) * HALO_W + tx];
#pragma unroll
            for (int dx = 0; dx < KS; ++dx) {
                const float s = srow[dx];
#pragma unroll
                for (int oo = 0; oo < OCPG; ++oo)
                    acc[oo] = fmaf(wr[oo * 9 + dy * 3 + dx], s, acc[oo]);
            }
        }

        float* orow = obase + (size_t)ty * Wd;
#pragma unroll
        for (int oo = 0; oo < OCPG; ++oo)
            orow[(size_t)oo * PLANE] = acc[oo];
    }
}

// ---------------------------------------------------------------------------
extern "C" void kernel_launch(void* const* d_in, const int* in_sizes, int n_in,
                              void* d_out, int out_size) {
    const float* x   = (const float*)d_in[0];
    const float* rep = (const float*)d_in[1];
    const float* W   = (const float*)d_in[2];
    float* out = (float*)d_out;

    gen_kernels<<<B, NK>>>(rep, W);

    dim3 grid(Wd / TX, H / TY, B * G);
    dyn_conv<<<grid, NTHR>>>(x, out);
}

// round 2
// speedup vs baseline: 1.3101x; 1.3101x over previous
#include <cuda_runtime.h>

// Problem constants
#define B       8
#define C       64
#define H       256
#define Wd      256
#define G       8
#define FPG     8
#define OCPG    8
#define KS      3
#define REPD    32
#define PLANE   (H * Wd)             // 65536
#define NWTS    (OCPG * KS * KS)     // 72 weights per (b,g)

// Tile config
#define TX      64
#define TY      32
#define NTHR    256
#define HALO_W  (TX + 2)             // 66
#define HALO_H  (TY + 2)             // 34

// ---------------------------------------------------------------------------
// Fused kernel: per-block weight generation + channel-sum + 3x3 dynamic conv
// grid: (W/TX, H/TY, B*G), block: 256 threads
// Each thread computes 2 output channels over a full 32-row column.
// ---------------------------------------------------------------------------
__global__ __launch_bounds__(NTHR, 4)
void dyn_conv(const float* __restrict__ x,
              const float* __restrict__ rep,
              const float* __restrict__ Wm,
              float* __restrict__ out) {
    const int bg = blockIdx.z;
    const int b  = bg >> 3;
    const int g  = bg & 7;
    const int x0 = blockIdx.x * TX;
    const int y0 = blockIdx.y * TY;
    const int t  = threadIdx.x;

    __shared__ float S[HALO_H * HALO_W];   // channel-summed halo tile
    __shared__ float wsh[NWTS];            // 72 dynamic weights for this (b,g)
    __shared__ float rsh[REPD];

    // ---- weight generation (fused, per block; W is L2-resident) ----
    if (t < REPD) rsh[t] = rep[b * REPD + t];
    __syncthreads();
    if (t < NWTS) {
        const float* wrow = Wm + (size_t)(g * NWTS + t) * REPD;
        float acc = 0.f;
#pragma unroll
        for (int j = 0; j < REPD; ++j) acc = fmaf(rsh[j], wrow[j], acc);
        wsh[t] = acc > 0.f ? acc : 0.1f * acc;
    }

    // ---- Phase 1: sum 8 group channels into smem halo tile ----
    const float* xbase = x + ((size_t)(b * C + g * FPG)) * PLANE;
    const int total = HALO_H * HALO_W;     // 2244
    for (int idx = t; idx < total; idx += NTHR) {
        const int r = idx / HALO_W;
        const int c = idx - r * HALO_W;
        int yy = y0 - 1 + r;
        yy = (yy < 0) ? -yy : yy;
        yy = (yy >= H) ? (2 * H - 2 - yy) : yy;
        int xx = x0 - 1 + c;
        xx = (xx < 0) ? -xx : xx;
        xx = (xx >= Wd) ? (2 * Wd - 2 - xx) : xx;
        const size_t off = (size_t)yy * Wd + xx;
        float s = 0.f;
#pragma unroll
        for (int ch = 0; ch < FPG; ++ch)
            s += xbase[(size_t)ch * PLANE + off];
        S[idx] = s;
    }
    __syncthreads();

    // ---- Phase 2: 3x3 conv, 2 output channels per thread, 32 rows ----
    const int tx = t & (TX - 1);           // x position within tile
    const int op = t >> 6;                 // 0..3 -> oc pair {2op, 2op+1}

    float w0[9], w1[9];
#pragma unroll
    for (int k = 0; k < 9; ++k) {
        w0[k] = wsh[(op * 2 + 0) * 9 + k];
        w1[k] = wsh[(op * 2 + 1) * 9 + k];
    }

    float* o0 = out + ((size_t)(b * C + g * OCPG + op * 2)) * PLANE
                    + (size_t)y0 * Wd + x0 + tx;
    float* o1 = o0 + PLANE;

    // sliding 3x3 window down the column
    float a0 = S[0 * HALO_W + tx], a1 = S[0 * HALO_W + tx + 1], a2 = S[0 * HALO_W + tx + 2];
    float m0 = S[1 * HALO_W + tx], m1 = S[1 * HALO_W + tx + 1], m2 = S[1 * HALO_W + tx + 2];

#pragma unroll
    for (int ty = 0; ty < TY; ++ty) {
        const float c0 = S[(ty + 2) * HALO_W + tx];
        const float c1 = S[(ty + 2) * HALO_W + tx + 1];
        const float c2 = S[(ty + 2) * HALO_W + tx + 2];

        float acc0, acc1;
        acc0 = w0[0] * a0;              acc1 = w1[0] * a0;
        acc0 = fmaf(w0[1], a1, acc0);   acc1 = fmaf(w1[1], a1, acc1);
        acc0 = fmaf(w0[2], a2, acc0);   acc1 = fmaf(w1[2], a2, acc1);
        acc0 = fmaf(w0[3], m0, acc0);   acc1 = fmaf(w1[3], m0, acc1);
        acc0 = fmaf(w0[4], m1, acc0);   acc1 = fmaf(w1[4], m1, acc1);
        acc0 = fmaf(w0[5], m2, acc0);   acc1 = fmaf(w1[5], m2, acc1);
        acc0 = fmaf(w0[6], c0, acc0);   acc1 = fmaf(w1[6], c0, acc1);
        acc0 = fmaf(w0[7], c1, acc0);   acc1 = fmaf(w1[7], c1, acc1);
        acc0 = fmaf(w0[8], c2, acc0);   acc1 = fmaf(w1[8], c2, acc1);

        o0[(size_t)ty * Wd] = acc0;
        o1[(size_t)ty * Wd] = acc1;

        a0 = m0; a1 = m1; a2 = m2;
        m0 = c0; m1 = c1; m2 = c2;
    }
}

// ---------------------------------------------------------------------------
extern "C" void kernel_launch(void* const* d_in, const int* in_sizes, int n_in,
                              void* d_out, int out_size) {
    const float* x   = (const float*)d_in[0];
    const float* rep = (const float*)d_in[1];
    const float* Wm  = (const float*)d_in[2];
    float* out = (float*)d_out;

    dim3 grid(Wd / TX, H / TY, B * G);
    dyn_conv<<<grid, NTHR>>>(x, rep, Wm, out);
}